// round 1
// baseline (speedup 1.0000x reference)
#include <cuda_runtime.h>
#include <cuda_bf16.h>
#include <cstdint>

// Problem shapes (fixed): N=2, T=16, S=256, D=1024
//   rows M = N*T*S = 8192
//   qkv: [8192, 3072]  layout per row: [q_s(512) | q_t(512) | k_s(512) | k_t(512) | v_s(512) | v_t(512)]
//   heads = 8, Dh = 64, scale = 0.125
//   attn buffer: [8192, 1024] = [x_s(512) | x_t(512)]

#define M_ROWS 8192
#define D_MODEL 1024
#define QKV_COLS 3072

__device__ float g_qkv[(size_t)M_ROWS * QKV_COLS];   // 96 MB scratch
__device__ float g_attn[(size_t)M_ROWS * D_MODEL];   // 32 MB scratch

// ---------------------------------------------------------------------------
// SGEMM: C[M,N] = A[M,K] @ B[K,N] (+ bias), all row-major fp32.
// 128x128 tile, BK=16, 256 threads, 8x8 register micro-tile.
// M % 128 == 0, N % 128 == 0, K % 16 == 0 assumed (true for both calls).
// ---------------------------------------------------------------------------
__global__ __launch_bounds__(256, 2)
void sgemm128(const float* __restrict__ A, const float* __restrict__ B,
              float* __restrict__ C, const float* __restrict__ bias,
              int M, int N, int K)
{
    constexpr int BM = 128, BN = 128, BK = 16;
    __shared__ float As[BK][BM];   // stored transposed: As[k][m]
    __shared__ float Bs[BK][BN];

    const int tid = threadIdx.x;
    const int tx = tid & 15;       // 0..15 -> 8 output cols each
    const int ty = tid >> 4;       // 0..15 -> 8 output rows each

    const float* Ab = A + (size_t)blockIdx.y * BM * K;
    const float* Bb = B + (size_t)blockIdx.x * BN;

    float acc[8][8];
#pragma unroll
    for (int i = 0; i < 8; i++)
#pragma unroll
        for (int j = 0; j < 8; j++) acc[i][j] = 0.f;

    for (int k0 = 0; k0 < K; k0 += BK) {
        // Load A tile (BM x BK = 2048 floats = 512 float4), store transposed.
#pragma unroll
        for (int s = tid; s < 512; s += 256) {
            int r = s >> 2;            // row in tile 0..127
            int c = (s & 3) * 4;       // k-col 0,4,8,12
            float4 v = *(const float4*)&Ab[(size_t)r * K + k0 + c];
            As[c + 0][r] = v.x;
            As[c + 1][r] = v.y;
            As[c + 2][r] = v.z;
            As[c + 3][r] = v.w;
        }
        // Load B tile (BK x BN = 2048 floats = 512 float4).
#pragma unroll
        for (int s = tid; s < 512; s += 256) {
            int r = s >> 5;            // k-row 0..15
            int c = (s & 31) * 4;      // col 0..124
            *(float4*)&Bs[r][c] = *(const float4*)&Bb[(size_t)(k0 + r) * N + c];
        }
        __syncthreads();

#pragma unroll
        for (int kk = 0; kk < BK; kk++) {
            float a[8], b[8];
            *(float4*)&a[0] = *(const float4*)&As[kk][ty * 8 + 0];
            *(float4*)&a[4] = *(const float4*)&As[kk][ty * 8 + 4];
            *(float4*)&b[0] = *(const float4*)&Bs[kk][tx * 8 + 0];
            *(float4*)&b[4] = *(const float4*)&Bs[kk][tx * 8 + 4];
#pragma unroll
            for (int i = 0; i < 8; i++)
#pragma unroll
                for (int j = 0; j < 8; j++)
                    acc[i][j] += a[i] * b[j];
        }
        __syncthreads();
    }

    const int row0 = blockIdx.y * BM + ty * 8;
    const int col0 = blockIdx.x * BN + tx * 8;
#pragma unroll
    for (int i = 0; i < 8; i++) {
#pragma unroll
        for (int j = 0; j < 8; j += 4) {
            float4 v;
            v.x = acc[i][j + 0];
            v.y = acc[i][j + 1];
            v.z = acc[i][j + 2];
            v.w = acc[i][j + 3];
            if (bias) {
                v.x += bias[col0 + j + 0];
                v.y += bias[col0 + j + 1];
                v.z += bias[col0 + j + 2];
                v.w += bias[col0 + j + 3];
            }
            *(float4*)&C[(size_t)(row0 + i) * N + col0 + j] = v;
        }
    }
}

// ---------------------------------------------------------------------------
// Spatial attention: per (n,t,h), q[256,64] vs k/v[256,64], softmax over keys.
// One block per (n,t,h) = 256 blocks; 256 threads, one query row per thread.
// K/V streamed through smem in 64-key chunks; online softmax in registers.
// ---------------------------------------------------------------------------
__global__ __launch_bounds__(256, 1)
void spatial_attn(const float* __restrict__ qkv, float* __restrict__ attn_out)
{
    const int b  = blockIdx.x;      // ((n*16+t)*8 + h)
    const int h  = b & 7;
    const int nt = b >> 3;
    const size_t RS = QKV_COLS;
    const size_t rowbase = (size_t)nt * 256;

    const float* Qp = qkv + rowbase * RS + 0    + h * 64;
    const float* Kp = qkv + rowbase * RS + 1024 + h * 64;
    const float* Vp = qkv + rowbase * RS + 2048 + h * 64;
    float*       Op = attn_out + rowbase * D_MODEL + h * 64;

    const int tid = threadIdx.x;    // query row within the frame

    float q[64];
#pragma unroll
    for (int d = 0; d < 64; d += 4) {
        float4 v = *(const float4*)&Qp[(size_t)tid * RS + d];
        q[d + 0] = v.x * 0.125f;
        q[d + 1] = v.y * 0.125f;
        q[d + 2] = v.z * 0.125f;
        q[d + 3] = v.w * 0.125f;
    }

    __shared__ float Ks[64][64];
    __shared__ float Vs[64][64];

    float m = -1e30f, l = 0.f;
    float o[64];
#pragma unroll
    for (int d = 0; d < 64; d++) o[d] = 0.f;

    for (int j0 = 0; j0 < 256; j0 += 64) {
        __syncthreads();
        // 64x64 floats each = 1024 float4 slots; 256 threads -> 4 each per matrix
        for (int s = tid; s < 64 * 16; s += 256) {
            int r = s >> 4;
            int c = (s & 15) * 4;
            *(float4*)&Ks[r][c] = *(const float4*)&Kp[(size_t)(j0 + r) * RS + c];
            *(float4*)&Vs[r][c] = *(const float4*)&Vp[(size_t)(j0 + r) * RS + c];
        }
        __syncthreads();

        for (int j = 0; j < 64; j++) {
            float sc = 0.f;
#pragma unroll
            for (int d = 0; d < 64; d++) sc += q[d] * Ks[j][d];
            if (sc > m) {
                float corr = __expf(m - sc);
                l *= corr;
#pragma unroll
                for (int d = 0; d < 64; d++) o[d] *= corr;
                m = sc;
            }
            float p = __expf(sc - m);
            l += p;
#pragma unroll
            for (int d = 0; d < 64; d++) o[d] += p * Vs[j][d];
        }
    }

    float inv = 1.f / l;
#pragma unroll
    for (int d = 0; d < 64; d += 4) {
        float4 v;
        v.x = o[d + 0] * inv;
        v.y = o[d + 1] * inv;
        v.z = o[d + 2] * inv;
        v.w = o[d + 3] * inv;
        *(float4*)&Op[(size_t)tid * D_MODEL + d] = v;
    }
}

// ---------------------------------------------------------------------------
// Temporal attention: per (n,s,h), q[16,64] vs k/v[16,64], softmax over the
// 16 temporal keys. One block per (n,s) = 512 blocks; 128 threads = (h, qt).
// ---------------------------------------------------------------------------
__global__ __launch_bounds__(128, 2)
void temporal_attn(const float* __restrict__ qkv, float* __restrict__ attn_out)
{
    const int b = blockIdx.x;       // n*256 + s
    const int n = b >> 8;
    const int s = b & 255;
    const int tid = threadIdx.x;    // h = tid>>4, qt = tid&15
    const int h  = tid >> 4;
    const int qt = tid & 15;
    const size_t RS = QKV_COLS;

    __shared__ float Ks[16][512];
    __shared__ float Vs[16][512];

    // Load all heads' k_t and v_t for the 16 frames at this (n,s).
    // 16*512 floats = 2048 float4 slots per matrix, 128 threads -> 16 each.
    for (int i = tid; i < 16 * 128; i += 128) {
        int t = i >> 7;
        int c = (i & 127) * 4;
        size_t row = ((size_t)(n * 16 + t) * 256 + s);
        *(float4*)&Ks[t][c] = *(const float4*)&qkv[row * RS + 1536 + c];
        *(float4*)&Vs[t][c] = *(const float4*)&qkv[row * RS + 2560 + c];
    }
    __syncthreads();

    float q[64];
    const size_t qrow = ((size_t)(n * 16 + qt) * 256 + s);
#pragma unroll
    for (int d = 0; d < 64; d += 4) {
        float4 v = *(const float4*)&qkv[qrow * RS + 512 + h * 64 + d];
        q[d + 0] = v.x * 0.125f;
        q[d + 1] = v.y * 0.125f;
        q[d + 2] = v.z * 0.125f;
        q[d + 3] = v.w * 0.125f;
    }

    float sc[16];
    float m = -1e30f;
#pragma unroll
    for (int t = 0; t < 16; t++) {
        float v = 0.f;
#pragma unroll
        for (int d = 0; d < 64; d++) v += q[d] * Ks[t][h * 64 + d];
        sc[t] = v;
        m = fmaxf(m, v);
    }
    float l = 0.f;
#pragma unroll
    for (int t = 0; t < 16; t++) { sc[t] = __expf(sc[t] - m); l += sc[t]; }
    float inv = 1.f / l;

    float* O = attn_out + qrow * D_MODEL + 512 + h * 64;
#pragma unroll
    for (int d = 0; d < 64; d += 4) {
        float4 v;
#pragma unroll
        for (int u = 0; u < 4; u++) {
            float acc = 0.f;
#pragma unroll
            for (int t = 0; t < 16; t++) acc += sc[t] * Vs[t][h * 64 + d + u];
            ((float*)&v)[u] = acc * inv;
        }
        *(float4*)&O[d] = v;
    }
}

// ---------------------------------------------------------------------------
extern "C" void kernel_launch(void* const* d_in, const int* in_sizes, int n_in,
                              void* d_out, int out_size)
{
    const float* x     = (const float*)d_in[0];   // [2,16,256,1024]
    const float* Wqkv  = (const float*)d_in[1];   // [1024,3072]
    const float* Wproj = (const float*)d_in[2];   // [1024,1024]
    const float* bproj = (const float*)d_in[3];   // [1024]
    float*       out   = (float*)d_out;           // [2,16,256,1024]

    float *qkv = nullptr, *attn = nullptr;
    cudaGetSymbolAddress((void**)&qkv,  g_qkv);
    cudaGetSymbolAddress((void**)&attn, g_attn);

    // 1) qkv = x @ Wqkv            [8192,1024] @ [1024,3072]
    {
        dim3 grid(QKV_COLS / 128, M_ROWS / 128);
        sgemm128<<<grid, 256>>>(x, Wqkv, qkv, nullptr, M_ROWS, QKV_COLS, D_MODEL);
    }
    // 2) spatial + temporal attention (independent, both read qkv)
    spatial_attn<<<256, 256>>>(qkv, attn);
    temporal_attn<<<512, 128>>>(qkv, attn);
    // 3) out = attn @ Wproj + bproj  [8192,1024] @ [1024,1024]
    {
        dim3 grid(D_MODEL / 128, M_ROWS / 128);
        sgemm128<<<grid, 256>>>(attn, Wproj, out, bproj, M_ROWS, D_MODEL, D_MODEL);
    }
}

// round 4
// speedup vs baseline: 2.5487x; 2.5487x over previous
#include <cuda_runtime.h>
#include <cuda_fp16.h>
#include <cstdint>

// Shapes fixed: N=2,T=16,S=256,D=1024 ; M=8192 rows
#define M_ROWS 8192
#define D_MODEL 1024
#define QKV_COLS 3072
#define KK 1024          // original K of both GEMMs
#define K2 2048          // doubled K for fp16 hi/lo split

__device__ float g_qkv[(size_t)M_ROWS * QKV_COLS];     // 96 MB
__device__ float g_attn[(size_t)M_ROWS * D_MODEL];     // 32 MB
__device__ __half g_Ah[(size_t)M_ROWS * K2];           // 32 MB  [a_hi | a_lo]
__device__ __half g_Bh[(size_t)QKV_COLS * K2];         // 12 MB  [b_hi | b_hi]

// ---------------------------------------------------------------- helpers
__device__ __forceinline__ uint32_t smem_u32(const void* p) {
    uint32_t a;
    asm("{ .reg .u64 t; cvta.to.shared.u64 t, %1; cvt.u32.u64 %0, t; }"
        : "=r"(a) : "l"(p));
    return a;
}
__device__ __forceinline__ void cpa16(uint32_t dst, const void* src) {
    asm volatile("cp.async.cg.shared.global [%0], [%1], 16;" :: "r"(dst), "l"(src) : "memory");
}
__device__ __forceinline__ void ldsm_x4(uint32_t addr, uint32_t& r0, uint32_t& r1,
                                        uint32_t& r2, uint32_t& r3) {
    asm volatile("ldmatrix.sync.aligned.m8n8.x4.shared.b16 {%0,%1,%2,%3}, [%4];"
                 : "=r"(r0), "=r"(r1), "=r"(r2), "=r"(r3) : "r"(addr));
}
__device__ __forceinline__ void mma16816(float* c, uint32_t a0, uint32_t a1,
                                         uint32_t a2, uint32_t a3,
                                         uint32_t b0, uint32_t b1) {
    asm volatile(
        "mma.sync.aligned.m16n8k16.row.col.f32.f16.f16.f32 "
        "{%0,%1,%2,%3}, {%4,%5,%6,%7}, {%8,%9}, {%0,%1,%2,%3};"
        : "+f"(c[0]), "+f"(c[1]), "+f"(c[2]), "+f"(c[3])
        : "r"(a0), "r"(a1), "r"(a2), "r"(a3), "r"(b0), "r"(b1));
}

// ---------------------------------------------------------------- conversions
// in [M,1024] fp32 -> out [M,2048] fp16 as [hi | lo]
__global__ __launch_bounds__(256)
void split_rows_h(const float* __restrict__ in, __half* __restrict__ out)
{
    size_t e = ((size_t)blockIdx.x * 256 + threadIdx.x) * 4;
    int m = (int)(e >> 10);
    int k = (int)(e & 1023);
    float4 v = *(const float4*)(in + e);
    __half h[4], l[4];
#pragma unroll
    for (int i = 0; i < 4; i++) {
        float a = ((const float*)&v)[i];
        __half hb = __float2half_rn(a);
        h[i] = hb;
        l[i] = __float2half_rn(a - __half2float(hb));
    }
    size_t ob = (size_t)m * K2 + k;
    *(uint2*)(out + ob) = *(uint2*)h;
    *(uint2*)(out + ob + 1024) = *(uint2*)l;
}

// W [1024, Ncols] fp32 row-major -> out [Ncols, 2048] fp16 as [hi | hi]
__global__ __launch_bounds__(256)
void transpose_split_h(const float* __restrict__ in, __half* __restrict__ out, int Ncols)
{
    __shared__ float t[32][33];
    int k0 = blockIdx.y * 32;
    int n0 = blockIdx.x * 32;
    int tx = threadIdx.x & 31;
    int ty = threadIdx.x >> 5;
#pragma unroll
    for (int dy = 0; dy < 32; dy += 8)
        t[ty + dy][tx] = in[(size_t)(k0 + ty + dy) * Ncols + n0 + tx];
    __syncthreads();
#pragma unroll
    for (int dy = 0; dy < 32; dy += 8) {
        int n = n0 + ty + dy;
        __half hb = __float2half_rn(t[tx][ty + dy]);
        size_t ob = (size_t)n * K2 + k0 + tx;
        out[ob] = hb;
        out[ob + 1024] = hb;
    }
}

// ---------------------------------------------------------------- HMMA GEMM
// C[M,N] = Ah[M,K2] * Bh[N,K2]^T (+bias), fp16 in, fp32 out. NT, K-major both.
// 128x128 tile, BK=32, 4-stage cp.async, 8 warps (2m x 4n), warp tile 64x32.
#define BK 32
#define NKT (K2 / BK)            // 64
#define ROWB 80                  // padded row: 32 halfs + 8 pad = 80 bytes
#define ATILE (128 * ROWB)       // 10240 B
#define STAGEB (2 * ATILE)       // 20480 B
#define NSTAGE 4
#define GSMEM (NSTAGE * STAGEB)  // 81920 B

__global__ __launch_bounds__(256)
void gemm_hmma(const __half* __restrict__ A, const __half* __restrict__ B,
               float* __restrict__ C, const float* __restrict__ bias, int N)
{
    extern __shared__ char smem[];
    const uint32_t sbase = smem_u32(smem);

    const int tid = threadIdx.x;
    const int wid = tid >> 5;
    const int lane = tid & 31;
    const int wm = wid & 1;          // 0..1  -> 64-row slice
    const int wn = wid >> 1;         // 0..3  -> 32-col slice
    const int m0 = blockIdx.y * 128;
    const int n0 = blockIdx.x * 128;

    const __half* Ag = A + (size_t)m0 * K2;
    const __half* Bg = B + (size_t)n0 * K2;

    float acc[4][4][4];
#pragma unroll
    for (int i = 0; i < 4; i++)
#pragma unroll
        for (int j = 0; j < 4; j++)
#pragma unroll
            for (int r = 0; r < 4; r++) acc[i][j][r] = 0.f;

    auto load_stage = [&](int kt) {
        const uint32_t sa = sbase + (kt & (NSTAGE - 1)) * STAGEB;
        const uint32_t sb = sa + ATILE;
        const int koff = kt * BK;
#pragma unroll
        for (int i = 0; i < 2; i++) {
            int u = tid + i * 256;
            int row = u >> 2, seg = u & 3;
            cpa16(sa + row * ROWB + seg * 16,
                  Ag + (size_t)row * K2 + koff + seg * 8);
        }
#pragma unroll
        for (int i = 0; i < 2; i++) {
            int u = tid + i * 256;
            int row = u >> 2, seg = u & 3;
            cpa16(sb + row * ROWB + seg * 16,
                  Bg + (size_t)row * K2 + koff + seg * 8);
        }
        asm volatile("cp.async.commit_group;" ::: "memory");
    };

    load_stage(0);
    load_stage(1);
    load_stage(2);

    // per-lane ldmatrix address components
    const int a_row_off = ((lane >> 3) & 1) * 8 + (lane & 7);   // + mfrag base
    const int a_k_off   = ((lane >> 4) & 1) * 8;                // + kstep*16
    const int b_row_off = ((lane >> 4) & 1) * 8 + (lane & 7);   // + nfrag-pair base
    const int b_k_off   = ((lane >> 3) & 1) * 8;

#pragma unroll 1
    for (int kt = 0; kt < NKT; kt++) {
        asm volatile("cp.async.wait_group 2;" ::: "memory");
        __syncthreads();
        const uint32_t sa = sbase + (kt & (NSTAGE - 1)) * STAGEB;
        const uint32_t sb = sa + ATILE;

#pragma unroll
        for (int ks = 0; ks < 2; ks++) {
            uint32_t af[4][4];
#pragma unroll
            for (int mi = 0; mi < 4; mi++) {
                uint32_t addr = sa + (wm * 64 + mi * 16 + a_row_off) * ROWB
                              + (ks * 16 + a_k_off) * 2;
                ldsm_x4(addr, af[mi][0], af[mi][1], af[mi][2], af[mi][3]);
            }
            uint32_t bf[4][2];
#pragma unroll
            for (int p = 0; p < 2; p++) {
                uint32_t addr = sb + (wn * 32 + p * 16 + b_row_off) * ROWB
                              + (ks * 16 + b_k_off) * 2;
                uint32_t r0, r1, r2, r3;
                ldsm_x4(addr, r0, r1, r2, r3);
                bf[p * 2 + 0][0] = r0; bf[p * 2 + 0][1] = r1;
                bf[p * 2 + 1][0] = r2; bf[p * 2 + 1][1] = r3;
            }
#pragma unroll
            for (int mi = 0; mi < 4; mi++)
#pragma unroll
                for (int ni = 0; ni < 4; ni++)
                    mma16816(acc[mi][ni], af[mi][0], af[mi][1], af[mi][2], af[mi][3],
                             bf[ni][0], bf[ni][1]);
        }

        if (kt + 3 < NKT) load_stage(kt + 3);
        else asm volatile("cp.async.commit_group;" ::: "memory");
    }

    // epilogue
    const int crow = lane >> 2;
    const int ccol = (lane & 3) * 2;
#pragma unroll
    for (int mi = 0; mi < 4; mi++) {
#pragma unroll
        for (int ni = 0; ni < 4; ni++) {
            int gm = m0 + wm * 64 + mi * 16 + crow;
            int gn = n0 + wn * 32 + ni * 8 + ccol;
            float b0 = 0.f, b1 = 0.f;
            if (bias) { b0 = bias[gn]; b1 = bias[gn + 1]; }
            float2 v0 = make_float2(acc[mi][ni][0] + b0, acc[mi][ni][1] + b1);
            float2 v1 = make_float2(acc[mi][ni][2] + b0, acc[mi][ni][3] + b1);
            *(float2*)&C[(size_t)gm * N + gn] = v0;
            *(float2*)&C[(size_t)(gm + 8) * N + gn] = v1;
        }
    }
}

// ---------------------------------------------------------------- attention
__global__ __launch_bounds__(256, 1)
void spatial_attn(const float* __restrict__ qkv, float* __restrict__ attn_out)
{
    const int b  = blockIdx.x;
    const int h  = b & 7;
    const int nt = b >> 3;
    const size_t RS = QKV_COLS;
    const size_t rowbase = (size_t)nt * 256;

    const float* Qp = qkv + rowbase * RS + 0    + h * 64;
    const float* Kp = qkv + rowbase * RS + 1024 + h * 64;
    const float* Vp = qkv + rowbase * RS + 2048 + h * 64;
    float*       Op = attn_out + rowbase * D_MODEL + h * 64;

    const int tid = threadIdx.x;

    float q[64];
#pragma unroll
    for (int d = 0; d < 64; d += 4) {
        float4 v = *(const float4*)&Qp[(size_t)tid * RS + d];
        q[d + 0] = v.x * 0.125f; q[d + 1] = v.y * 0.125f;
        q[d + 2] = v.z * 0.125f; q[d + 3] = v.w * 0.125f;
    }

    __shared__ float Ks[64][64];
    __shared__ float Vs[64][64];

    float m = -1e30f, l = 0.f;
    float o[64];
#pragma unroll
    for (int d = 0; d < 64; d++) o[d] = 0.f;

    for (int j0 = 0; j0 < 256; j0 += 64) {
        __syncthreads();
        for (int s = tid; s < 64 * 16; s += 256) {
            int r = s >> 4;
            int c = (s & 15) * 4;
            *(float4*)&Ks[r][c] = *(const float4*)&Kp[(size_t)(j0 + r) * RS + c];
            *(float4*)&Vs[r][c] = *(const float4*)&Vp[(size_t)(j0 + r) * RS + c];
        }
        __syncthreads();

        for (int j = 0; j < 64; j++) {
            float sc = 0.f;
#pragma unroll
            for (int d = 0; d < 64; d++) sc += q[d] * Ks[j][d];
            if (sc > m) {
                float corr = __expf(m - sc);
                l *= corr;
#pragma unroll
                for (int d = 0; d < 64; d++) o[d] *= corr;
                m = sc;
            }
            float p = __expf(sc - m);
            l += p;
#pragma unroll
            for (int d = 0; d < 64; d++) o[d] += p * Vs[j][d];
        }
    }

    float inv = 1.f / l;
#pragma unroll
    for (int d = 0; d < 64; d += 4) {
        float4 v;
        v.x = o[d + 0] * inv; v.y = o[d + 1] * inv;
        v.z = o[d + 2] * inv; v.w = o[d + 3] * inv;
        *(float4*)&Op[(size_t)tid * D_MODEL + d] = v;
    }
}

__global__ __launch_bounds__(128, 2)
void temporal_attn(const float* __restrict__ qkv, float* __restrict__ attn_out)
{
    const int b = blockIdx.x;
    const int n = b >> 8;
    const int s = b & 255;
    const int tid = threadIdx.x;
    const int h  = tid >> 4;
    const int qt = tid & 15;
    const size_t RS = QKV_COLS;

    __shared__ float Ks[16][512];
    __shared__ float Vs[16][512];

    for (int i = tid; i < 16 * 128; i += 128) {
        int t = i >> 7;
        int c = (i & 127) * 4;
        size_t row = ((size_t)(n * 16 + t) * 256 + s);
        *(float4*)&Ks[t][c] = *(const float4*)&qkv[row * RS + 1536 + c];
        *(float4*)&Vs[t][c] = *(const float4*)&qkv[row * RS + 2560 + c];
    }
    __syncthreads();

    float q[64];
    const size_t qrow = ((size_t)(n * 16 + qt) * 256 + s);
#pragma unroll
    for (int d = 0; d < 64; d += 4) {
        float4 v = *(const float4*)&qkv[qrow * RS + 512 + h * 64 + d];
        q[d + 0] = v.x * 0.125f; q[d + 1] = v.y * 0.125f;
        q[d + 2] = v.z * 0.125f; q[d + 3] = v.w * 0.125f;
    }

    float sc[16];
    float m = -1e30f;
#pragma unroll
    for (int t = 0; t < 16; t++) {
        float v = 0.f;
#pragma unroll
        for (int d = 0; d < 64; d++) v += q[d] * Ks[t][h * 64 + d];
        sc[t] = v;
        m = fmaxf(m, v);
    }
    float l = 0.f;
#pragma unroll
    for (int t = 0; t < 16; t++) { sc[t] = __expf(sc[t] - m); l += sc[t]; }
    float inv = 1.f / l;

    float* O = attn_out + qrow * D_MODEL + 512 + h * 64;
#pragma unroll
    for (int d = 0; d < 64; d += 4) {
        float4 v;
#pragma unroll
        for (int u = 0; u < 4; u++) {
            float acc = 0.f;
#pragma unroll
            for (int t = 0; t < 16; t++) acc += sc[t] * Vs[t][h * 64 + d + u];
            ((float*)&v)[u] = acc * inv;
        }
        *(float4*)&O[d] = v;
    }
}

// ---------------------------------------------------------------- launch
extern "C" void kernel_launch(void* const* d_in, const int* in_sizes, int n_in,
                              void* d_out, int out_size)
{
    const float* x     = (const float*)d_in[0];
    const float* Wqkv  = (const float*)d_in[1];
    const float* Wproj = (const float*)d_in[2];
    const float* bproj = (const float*)d_in[3];
    float*       out   = (float*)d_out;

    float *qkv = nullptr, *attn = nullptr;
    __half *Ah = nullptr, *Bh = nullptr;
    cudaGetSymbolAddress((void**)&qkv,  g_qkv);
    cudaGetSymbolAddress((void**)&attn, g_attn);
    cudaGetSymbolAddress((void**)&Ah,   g_Ah);
    cudaGetSymbolAddress((void**)&Bh,   g_Bh);

    cudaFuncSetAttribute(gemm_hmma, cudaFuncAttributeMaxDynamicSharedMemorySize, GSMEM);

    // GEMM1: qkv = x @ Wqkv  (fp16 split over K2)
    split_rows_h<<<(M_ROWS * KK / 4) / 256, 256>>>(x, Ah);
    transpose_split_h<<<dim3(QKV_COLS / 32, KK / 32), 256>>>(Wqkv, Bh, QKV_COLS);
    gemm_hmma<<<dim3(QKV_COLS / 128, M_ROWS / 128), 256, GSMEM>>>(Ah, Bh, qkv, nullptr, QKV_COLS);

    // attention
    spatial_attn<<<256, 256>>>(qkv, attn);
    temporal_attn<<<512, 128>>>(qkv, attn);

    // GEMM2: out = attn @ Wproj + bproj
    split_rows_h<<<(M_ROWS * KK / 4) / 256, 256>>>(attn, Ah);
    transpose_split_h<<<dim3(D_MODEL / 32, KK / 32), 256>>>(Wproj, Bh, D_MODEL);
    gemm_hmma<<<dim3(D_MODEL / 128, M_ROWS / 128), 256, GSMEM>>>(Ah, Bh, out, bproj, D_MODEL);
}

// round 7
// speedup vs baseline: 3.2924x; 1.2918x over previous
#include <cuda_runtime.h>
#include <cuda_fp16.h>
#include <cstdint>

// Shapes fixed: N=2,T=16,S=256,D=1024 ; M=8192 rows
#define M_ROWS 8192
#define D_MODEL 1024
#define QKV_COLS 3072
#define KK 1024          // original K of both GEMMs
#define K2 2048          // doubled K for fp16 hi/lo split

__device__ float g_qkv[(size_t)M_ROWS * QKV_COLS];     // 96 MB
__device__ float g_attn[(size_t)M_ROWS * D_MODEL];     // 32 MB
__device__ __half g_Ah[(size_t)M_ROWS * K2];           // 32 MB  [a_hi | a_lo]
__device__ __half g_Bh[(size_t)QKV_COLS * K2];         // 12 MB  [b_hi | b_hi]

// ---------------------------------------------------------------- helpers
__device__ __forceinline__ uint32_t smem_u32(const void* p) {
    uint32_t a;
    asm("{ .reg .u64 t; cvta.to.shared.u64 t, %1; cvt.u32.u64 %0, t; }"
        : "=r"(a) : "l"(p));
    return a;
}
__device__ __forceinline__ void cpa16(uint32_t dst, const void* src) {
    asm volatile("cp.async.cg.shared.global [%0], [%1], 16;" :: "r"(dst), "l"(src) : "memory");
}
__device__ __forceinline__ void ldsm_x4(uint32_t addr, uint32_t& r0, uint32_t& r1,
                                        uint32_t& r2, uint32_t& r3) {
    asm volatile("ldmatrix.sync.aligned.m8n8.x4.shared.b16 {%0,%1,%2,%3}, [%4];"
                 : "=r"(r0), "=r"(r1), "=r"(r2), "=r"(r3) : "r"(addr));
}
__device__ __forceinline__ void ldsm_x4_t(uint32_t addr, uint32_t& r0, uint32_t& r1,
                                          uint32_t& r2, uint32_t& r3) {
    asm volatile("ldmatrix.sync.aligned.m8n8.x4.trans.shared.b16 {%0,%1,%2,%3}, [%4];"
                 : "=r"(r0), "=r"(r1), "=r"(r2), "=r"(r3) : "r"(addr));
}
__device__ __forceinline__ void mma16816(float* c, uint32_t a0, uint32_t a1,
                                         uint32_t a2, uint32_t a3,
                                         uint32_t b0, uint32_t b1) {
    asm volatile(
        "mma.sync.aligned.m16n8k16.row.col.f32.f16.f16.f32 "
        "{%0,%1,%2,%3}, {%4,%5,%6,%7}, {%8,%9}, {%0,%1,%2,%3};"
        : "+f"(c[0]), "+f"(c[1]), "+f"(c[2]), "+f"(c[3])
        : "r"(a0), "r"(a1), "r"(a2), "r"(a3), "r"(b0), "r"(b1));
}
// pack two fp32 -> one reg of half2 {lo=a0, hi=a1}
__device__ __forceinline__ uint32_t packh2(float lo, float hi) {
    uint32_t d;
    asm("cvt.rn.f16x2.f32 %0, %1, %2;" : "=r"(d) : "f"(hi), "f"(lo));
    return d;
}

// ---------------------------------------------------------------- conversions
// in [M,1024] fp32 -> out [M,2048] fp16 as [hi | lo]
__global__ __launch_bounds__(256)
void split_rows_h(const float* __restrict__ in, __half* __restrict__ out)
{
    size_t e = ((size_t)blockIdx.x * 256 + threadIdx.x) * 4;
    int m = (int)(e >> 10);
    int k = (int)(e & 1023);
    float4 v = *(const float4*)(in + e);
    __half h[4], l[4];
#pragma unroll
    for (int i = 0; i < 4; i++) {
        float a = ((const float*)&v)[i];
        __half hb = __float2half_rn(a);
        h[i] = hb;
        l[i] = __float2half_rn(a - __half2float(hb));
    }
    size_t ob = (size_t)m * K2 + k;
    *(uint2*)(out + ob) = *(uint2*)h;
    *(uint2*)(out + ob + 1024) = *(uint2*)l;
}

// W [1024, Ncols] fp32 row-major -> out [Ncols, 2048] fp16 as [hi | hi]
__global__ __launch_bounds__(256)
void transpose_split_h(const float* __restrict__ in, __half* __restrict__ out, int Ncols)
{
    __shared__ float t[32][33];
    int k0 = blockIdx.y * 32;
    int n0 = blockIdx.x * 32;
    int tx = threadIdx.x & 31;
    int ty = threadIdx.x >> 5;
#pragma unroll
    for (int dy = 0; dy < 32; dy += 8)
        t[ty + dy][tx] = in[(size_t)(k0 + ty + dy) * Ncols + n0 + tx];
    __syncthreads();
#pragma unroll
    for (int dy = 0; dy < 32; dy += 8) {
        int n = n0 + ty + dy;
        __half hb = __float2half_rn(t[tx][ty + dy]);
        size_t ob = (size_t)n * K2 + k0 + tx;
        out[ob] = hb;
        out[ob + 1024] = hb;
    }
}

// ---------------------------------------------------------------- HMMA GEMM
#define BK 32
#define NKT (K2 / BK)            // 64
#define ROWB 80                  // padded row: 32 halfs + 8 pad = 80 bytes
#define ATILE (128 * ROWB)       // 10240 B
#define STAGEB (2 * ATILE)       // 20480 B
#define NSTAGE 4
#define GSMEM (NSTAGE * STAGEB)  // 81920 B

__global__ __launch_bounds__(256)
void gemm_hmma(const __half* __restrict__ A, const __half* __restrict__ B,
               float* __restrict__ C, const float* __restrict__ bias, int N)
{
    extern __shared__ char smem[];
    const uint32_t sbase = smem_u32(smem);

    const int tid = threadIdx.x;
    const int wid = tid >> 5;
    const int lane = tid & 31;
    const int wm = wid & 1;
    const int wn = wid >> 1;
    const int m0 = blockIdx.y * 128;
    const int n0 = blockIdx.x * 128;

    const __half* Ag = A + (size_t)m0 * K2;
    const __half* Bg = B + (size_t)n0 * K2;

    float acc[4][4][4];
#pragma unroll
    for (int i = 0; i < 4; i++)
#pragma unroll
        for (int j = 0; j < 4; j++)
#pragma unroll
            for (int r = 0; r < 4; r++) acc[i][j][r] = 0.f;

    auto load_stage = [&](int kt) {
        const uint32_t sa = sbase + (kt & (NSTAGE - 1)) * STAGEB;
        const uint32_t sb = sa + ATILE;
        const int koff = kt * BK;
#pragma unroll
        for (int i = 0; i < 2; i++) {
            int u = tid + i * 256;
            int row = u >> 2, seg = u & 3;
            cpa16(sa + row * ROWB + seg * 16,
                  Ag + (size_t)row * K2 + koff + seg * 8);
        }
#pragma unroll
        for (int i = 0; i < 2; i++) {
            int u = tid + i * 256;
            int row = u >> 2, seg = u & 3;
            cpa16(sb + row * ROWB + seg * 16,
                  Bg + (size_t)row * K2 + koff + seg * 8);
        }
        asm volatile("cp.async.commit_group;" ::: "memory");
    };

    load_stage(0);
    load_stage(1);
    load_stage(2);

    const int a_row_off = ((lane >> 3) & 1) * 8 + (lane & 7);
    const int a_k_off   = ((lane >> 4) & 1) * 8;
    const int b_row_off = ((lane >> 4) & 1) * 8 + (lane & 7);
    const int b_k_off   = ((lane >> 3) & 1) * 8;

#pragma unroll 1
    for (int kt = 0; kt < NKT; kt++) {
        asm volatile("cp.async.wait_group 2;" ::: "memory");
        __syncthreads();
        const uint32_t sa = sbase + (kt & (NSTAGE - 1)) * STAGEB;
        const uint32_t sb = sa + ATILE;

#pragma unroll
        for (int ks = 0; ks < 2; ks++) {
            uint32_t af[4][4];
#pragma unroll
            for (int mi = 0; mi < 4; mi++) {
                uint32_t addr = sa + (wm * 64 + mi * 16 + a_row_off) * ROWB
                              + (ks * 16 + a_k_off) * 2;
                ldsm_x4(addr, af[mi][0], af[mi][1], af[mi][2], af[mi][3]);
            }
            uint32_t bf[4][2];
#pragma unroll
            for (int p = 0; p < 2; p++) {
                uint32_t addr = sb + (wn * 32 + p * 16 + b_row_off) * ROWB
                              + (ks * 16 + b_k_off) * 2;
                uint32_t r0, r1, r2, r3;
                ldsm_x4(addr, r0, r1, r2, r3);
                bf[p * 2 + 0][0] = r0; bf[p * 2 + 0][1] = r1;
                bf[p * 2 + 1][0] = r2; bf[p * 2 + 1][1] = r3;
            }
#pragma unroll
            for (int mi = 0; mi < 4; mi++)
#pragma unroll
                for (int ni = 0; ni < 4; ni++)
                    mma16816(acc[mi][ni], af[mi][0], af[mi][1], af[mi][2], af[mi][3],
                             bf[ni][0], bf[ni][1]);
        }

        if (kt + 3 < NKT) load_stage(kt + 3);
        else asm volatile("cp.async.commit_group;" ::: "memory");
    }

    const int crow = lane >> 2;
    const int ccol = (lane & 3) * 2;
#pragma unroll
    for (int mi = 0; mi < 4; mi++) {
#pragma unroll
        for (int ni = 0; ni < 4; ni++) {
            int gm = m0 + wm * 64 + mi * 16 + crow;
            int gn = n0 + wn * 32 + ni * 8 + ccol;
            float b0 = 0.f, b1 = 0.f;
            if (bias) { b0 = bias[gn]; b1 = bias[gn + 1]; }
            float2 v0 = make_float2(acc[mi][ni][0] + b0, acc[mi][ni][1] + b1);
            float2 v1 = make_float2(acc[mi][ni][2] + b0, acc[mi][ni][3] + b1);
            *(float2*)&C[(size_t)gm * N + gn] = v0;
            *(float2*)&C[(size_t)(gm + 8) * N + gn] = v1;
        }
    }
}

// ---------------------------------------------------------------- spatial attention (HMMA flash)
// Per block: (nt, h, qhalf) -> 128 queries x 256 keys, Dh=64.
// 4 warps x 32 queries. K/V in 64-key tiles. fp16 mma, fp32 online softmax.
#define AROW 72                       // 64 halfs + 8 pad (144 B rows)
__global__ __launch_bounds__(128)
void spatial_attn_h(const float* __restrict__ qkv, float* __restrict__ attn_out)
{
    const int b  = blockIdx.x;        // nt*16 + h*2 + qh
    const int qh = b & 1;
    const int h  = (b >> 1) & 7;
    const int nt = b >> 4;
    const size_t RS = QKV_COLS;
    const size_t rowbase = (size_t)nt * 256;
    const int q0 = qh * 128;

    __shared__ __half Qs[128 * AROW];
    __shared__ __half Ks[64 * AROW];
    __shared__ __half Vs[64 * AROW];

    const int tid  = threadIdx.x;
    const int warp = tid >> 5;
    const int lane = tid & 31;

    // load Q (scaled by 0.125), fp32 -> fp16 smem
    for (int i = tid; i < 128 * 16; i += 128) {
        int r = i >> 4, c = (i & 15) * 4;
        float4 v = *(const float4*)&qkv[(rowbase + q0 + r) * RS + h * 64 + c];
        __half* dst = &Qs[r * AROW + c];
        dst[0] = __float2half_rn(v.x * 0.125f);
        dst[1] = __float2half_rn(v.y * 0.125f);
        dst[2] = __float2half_rn(v.z * 0.125f);
        dst[3] = __float2half_rn(v.w * 0.125f);
    }

    const uint32_t qbase = smem_u32(Qs);
    const uint32_t kbase = smem_u32(Ks);
    const uint32_t vbase = smem_u32(Vs);

    const int a_row_off = ((lane >> 3) & 1) * 8 + (lane & 7);
    const int a_k_off   = ((lane >> 4) & 1) * 8;
    const int b_row_off = ((lane >> 4) & 1) * 8 + (lane & 7);
    const int b_k_off   = ((lane >> 3) & 1) * 8;
    // V trans ldsm per-lane address parts
    const int v_mat = lane >> 3;
    const int v_row_off = (v_mat & 1) * 8 + (lane & 7);
    const int v_col_off = (v_mat >> 1) * 8;

    float o[2][8][4];
#pragma unroll
    for (int mi = 0; mi < 2; mi++)
#pragma unroll
        for (int ni = 0; ni < 8; ni++)
#pragma unroll
            for (int r = 0; r < 4; r++) o[mi][ni][r] = 0.f;
    float mst[2][2] = {{-1e30f, -1e30f}, {-1e30f, -1e30f}};
    float lst[2][2] = {{0.f, 0.f}, {0.f, 0.f}};

    for (int t = 0; t < 4; t++) {
        __syncthreads();
        const int j0 = t * 64;
        for (int i = tid; i < 64 * 16; i += 128) {
            int r = i >> 4, c = (i & 15) * 4;
            float4 kv = *(const float4*)&qkv[(rowbase + j0 + r) * RS + 1024 + h * 64 + c];
            float4 vv = *(const float4*)&qkv[(rowbase + j0 + r) * RS + 2048 + h * 64 + c];
            __half* kd = &Ks[r * AROW + c];
            __half* vd = &Vs[r * AROW + c];
            kd[0] = __float2half_rn(kv.x); kd[1] = __float2half_rn(kv.y);
            kd[2] = __float2half_rn(kv.z); kd[3] = __float2half_rn(kv.w);
            vd[0] = __float2half_rn(vv.x); vd[1] = __float2half_rn(vv.y);
            vd[2] = __float2half_rn(vv.z); vd[3] = __float2half_rn(vv.w);
        }
        __syncthreads();

        // ---- S = Q K^T  (32 x 64 per warp)
        float s[2][8][4];
#pragma unroll
        for (int mi = 0; mi < 2; mi++)
#pragma unroll
            for (int ni = 0; ni < 8; ni++)
#pragma unroll
                for (int r = 0; r < 4; r++) s[mi][ni][r] = 0.f;

#pragma unroll
        for (int kk = 0; kk < 4; kk++) {
            uint32_t af[2][4];
#pragma unroll
            for (int mi = 0; mi < 2; mi++) {
                uint32_t addr = qbase + (warp * 32 + mi * 16 + a_row_off) * (AROW * 2)
                              + (kk * 16 + a_k_off) * 2;
                ldsm_x4(addr, af[mi][0], af[mi][1], af[mi][2], af[mi][3]);
            }
            uint32_t bf[8][2];
#pragma unroll
            for (int kb = 0; kb < 4; kb++) {
                uint32_t addr = kbase + (kb * 16 + b_row_off) * (AROW * 2)
                              + (kk * 16 + b_k_off) * 2;
                uint32_t r0, r1, r2, r3;
                ldsm_x4(addr, r0, r1, r2, r3);
                bf[kb * 2 + 0][0] = r0; bf[kb * 2 + 0][1] = r1;
                bf[kb * 2 + 1][0] = r2; bf[kb * 2 + 1][1] = r3;
            }
#pragma unroll
            for (int mi = 0; mi < 2; mi++)
#pragma unroll
                for (int ni = 0; ni < 8; ni++)
                    mma16816(s[mi][ni], af[mi][0], af[mi][1], af[mi][2], af[mi][3],
                             bf[ni][0], bf[ni][1]);
        }

        // ---- online softmax update
#pragma unroll
        for (int mi = 0; mi < 2; mi++) {
#pragma unroll
            for (int half = 0; half < 2; half++) {
                float mx = -1e30f;
#pragma unroll
                for (int ni = 0; ni < 8; ni++) {
                    mx = fmaxf(mx, s[mi][ni][half * 2 + 0]);
                    mx = fmaxf(mx, s[mi][ni][half * 2 + 1]);
                }
                mx = fmaxf(mx, __shfl_xor_sync(0xffffffffu, mx, 1));
                mx = fmaxf(mx, __shfl_xor_sync(0xffffffffu, mx, 2));
                float m_new = fmaxf(mst[mi][half], mx);
                float corr = __expf(mst[mi][half] - m_new);
                float sum = 0.f;
#pragma unroll
                for (int ni = 0; ni < 8; ni++) {
                    float p0 = __expf(s[mi][ni][half * 2 + 0] - m_new);
                    float p1 = __expf(s[mi][ni][half * 2 + 1] - m_new);
                    s[mi][ni][half * 2 + 0] = p0;
                    s[mi][ni][half * 2 + 1] = p1;
                    sum += p0 + p1;
                }
                sum += __shfl_xor_sync(0xffffffffu, sum, 1);
                sum += __shfl_xor_sync(0xffffffffu, sum, 2);
                lst[mi][half] = lst[mi][half] * corr + sum;
                mst[mi][half] = m_new;
#pragma unroll
                for (int ni = 0; ni < 8; ni++) {
                    o[mi][ni][half * 2 + 0] *= corr;
                    o[mi][ni][half * 2 + 1] *= corr;
                }
            }
        }

        // ---- O += P V  (P from accum frags, V via ldmatrix.trans)
#pragma unroll
        for (int kk = 0; kk < 4; kk++) {
            uint32_t pa[2][4];
#pragma unroll
            for (int mi = 0; mi < 2; mi++) {
                pa[mi][0] = packh2(s[mi][kk * 2 + 0][0], s[mi][kk * 2 + 0][1]);
                pa[mi][1] = packh2(s[mi][kk * 2 + 0][2], s[mi][kk * 2 + 0][3]);
                pa[mi][2] = packh2(s[mi][kk * 2 + 1][0], s[mi][kk * 2 + 1][1]);
                pa[mi][3] = packh2(s[mi][kk * 2 + 1][2], s[mi][kk * 2 + 1][3]);
            }
#pragma unroll
            for (int nb = 0; nb < 4; nb++) {
                uint32_t addr = vbase + (kk * 16 + v_row_off) * (AROW * 2)
                              + (nb * 16 + v_col_off) * 2;
                uint32_t b0, b1, b2, b3;
                ldsm_x4_t(addr, b0, b1, b2, b3);
#pragma unroll
                for (int mi = 0; mi < 2; mi++) {
                    mma16816(o[mi][nb * 2 + 0], pa[mi][0], pa[mi][1], pa[mi][2], pa[mi][3], b0, b1);
                    mma16816(o[mi][nb * 2 + 1], pa[mi][0], pa[mi][1], pa[mi][2], pa[mi][3], b2, b3);
                }
            }
        }
    }

    // ---- finalize and store
    const int crow = lane >> 2;
    const int ccol = (lane & 3) * 2;
#pragma unroll
    for (int mi = 0; mi < 2; mi++) {
        float inv0 = 1.f / lst[mi][0];
        float inv1 = 1.f / lst[mi][1];
        int row = q0 + warp * 32 + mi * 16 + crow;
#pragma unroll
        for (int ni = 0; ni < 8; ni++) {
            int col = h * 64 + ni * 8 + ccol;
            float2 v0 = make_float2(o[mi][ni][0] * inv0, o[mi][ni][1] * inv0);
            float2 v1 = make_float2(o[mi][ni][2] * inv1, o[mi][ni][3] * inv1);
            *(float2*)&attn_out[(rowbase + row) * D_MODEL + col] = v0;
            *(float2*)&attn_out[(rowbase + row + 8) * D_MODEL + col] = v1;
        }
    }
}

// ---------------------------------------------------------------- temporal attention (fp32)
__global__ __launch_bounds__(128, 2)
void temporal_attn(const float* __restrict__ qkv, float* __restrict__ attn_out)
{
    const int b = blockIdx.x;
    const int n = b >> 8;
    const int s = b & 255;
    const int tid = threadIdx.x;
    const int h  = tid >> 4;
    const int qt = tid & 15;
    const size_t RS = QKV_COLS;

    __shared__ float Ks[16][512];
    __shared__ float Vs[16][512];

    for (int i = tid; i < 16 * 128; i += 128) {
        int t = i >> 7;
        int c = (i & 127) * 4;
        size_t row = ((size_t)(n * 16 + t) * 256 + s);
        *(float4*)&Ks[t][c] = *(const float4*)&qkv[row * RS + 1536 + c];
        *(float4*)&Vs[t][c] = *(const float4*)&qkv[row * RS + 2560 + c];
    }
    __syncthreads();

    float q[64];
    const size_t qrow = ((size_t)(n * 16 + qt) * 256 + s);
#pragma unroll
    for (int d = 0; d < 64; d += 4) {
        float4 v = *(const float4*)&qkv[qrow * RS + 512 + h * 64 + d];
        q[d + 0] = v.x * 0.125f; q[d + 1] = v.y * 0.125f;
        q[d + 2] = v.z * 0.125f; q[d + 3] = v.w * 0.125f;
    }

    float sc[16];
    float m = -1e30f;
#pragma unroll
    for (int t = 0; t < 16; t++) {
        float v = 0.f;
#pragma unroll
        for (int d = 0; d < 64; d++) v += q[d] * Ks[t][h * 64 + d];
        sc[t] = v;
        m = fmaxf(m, v);
    }
    float l = 0.f;
#pragma unroll
    for (int t = 0; t < 16; t++) { sc[t] = __expf(sc[t] - m); l += sc[t]; }
    float inv = 1.f / l;

    float* O = attn_out + qrow * D_MODEL + 512 + h * 64;
#pragma unroll
    for (int d = 0; d < 64; d += 4) {
        float4 v;
#pragma unroll
        for (int u = 0; u < 4; u++) {
            float acc = 0.f;
#pragma unroll
            for (int t = 0; t < 16; t++) acc += sc[t] * Vs[t][h * 64 + d + u];
            ((float*)&v)[u] = acc * inv;
        }
        *(float4*)&O[d] = v;
    }
}

// ---------------------------------------------------------------- launch
extern "C" void kernel_launch(void* const* d_in, const int* in_sizes, int n_in,
                              void* d_out, int out_size)
{
    const float* x     = (const float*)d_in[0];
    const float* Wqkv  = (const float*)d_in[1];
    const float* Wproj = (const float*)d_in[2];
    const float* bproj = (const float*)d_in[3];
    float*       out   = (float*)d_out;

    float *qkv = nullptr, *attn = nullptr;
    __half *Ah = nullptr, *Bh = nullptr;
    cudaGetSymbolAddress((void**)&qkv,  g_qkv);
    cudaGetSymbolAddress((void**)&attn, g_attn);
    cudaGetSymbolAddress((void**)&Ah,   g_Ah);
    cudaGetSymbolAddress((void**)&Bh,   g_Bh);

    cudaFuncSetAttribute(gemm_hmma, cudaFuncAttributeMaxDynamicSharedMemorySize, GSMEM);

    // GEMM1: qkv = x @ Wqkv  (fp16 split over K2)
    split_rows_h<<<(M_ROWS * KK / 4) / 256, 256>>>(x, Ah);
    transpose_split_h<<<dim3(QKV_COLS / 32, KK / 32), 256>>>(Wqkv, Bh, QKV_COLS);
    gemm_hmma<<<dim3(QKV_COLS / 128, M_ROWS / 128), 256, GSMEM>>>(Ah, Bh, qkv, nullptr, QKV_COLS);

    // attention
    spatial_attn_h<<<512, 128>>>(qkv, attn);
    temporal_attn<<<512, 128>>>(qkv, attn);

    // GEMM2: out = attn @ Wproj + bproj
    split_rows_h<<<(M_ROWS * KK / 4) / 256, 256>>>(attn, Ah);
    transpose_split_h<<<dim3(D_MODEL / 32, KK / 32), 256>>>(Wproj, Bh, D_MODEL);
    gemm_hmma<<<dim3(D_MODEL / 128, M_ROWS / 128), 256, GSMEM>>>(Ah, Bh, out, bproj, D_MODEL);
}

// round 9
// speedup vs baseline: 3.5216x; 1.0696x over previous
#include <cuda_runtime.h>
#include <cuda_fp16.h>
#include <cstdint>

// Shapes fixed: N=2,T=16,S=256,D=1024 ; M=8192 rows
#define M_ROWS 8192
#define D_MODEL 1024
#define QKV_COLS 3072
#define KK 1024          // original K of both GEMMs
#define K2 2048          // doubled K for fp16 hi/lo split

__device__ __half g_qkvh[(size_t)M_ROWS * QKV_COLS];   // 48 MB  fp16 qkv
__device__ __half g_Ah[(size_t)M_ROWS * K2];           // 32 MB  [hi | lo]
__device__ __half g_Bh[(size_t)QKV_COLS * K2];         // 12 MB  [hi | hi]

// ---------------------------------------------------------------- helpers
__device__ __forceinline__ uint32_t smem_u32(const void* p) {
    uint32_t a;
    asm("{ .reg .u64 t; cvta.to.shared.u64 t, %1; cvt.u32.u64 %0, t; }"
        : "=r"(a) : "l"(p));
    return a;
}
__device__ __forceinline__ void cpa16(uint32_t dst, const void* src) {
    asm volatile("cp.async.cg.shared.global [%0], [%1], 16;" :: "r"(dst), "l"(src) : "memory");
}
#define CP_COMMIT() asm volatile("cp.async.commit_group;" ::: "memory")
__device__ __forceinline__ void ldsm_x4(uint32_t addr, uint32_t& r0, uint32_t& r1,
                                        uint32_t& r2, uint32_t& r3) {
    asm volatile("ldmatrix.sync.aligned.m8n8.x4.shared.b16 {%0,%1,%2,%3}, [%4];"
                 : "=r"(r0), "=r"(r1), "=r"(r2), "=r"(r3) : "r"(addr));
}
__device__ __forceinline__ void ldsm_x4_t(uint32_t addr, uint32_t& r0, uint32_t& r1,
                                          uint32_t& r2, uint32_t& r3) {
    asm volatile("ldmatrix.sync.aligned.m8n8.x4.trans.shared.b16 {%0,%1,%2,%3}, [%4];"
                 : "=r"(r0), "=r"(r1), "=r"(r2), "=r"(r3) : "r"(addr));
}
__device__ __forceinline__ void mma16816(float* c, uint32_t a0, uint32_t a1,
                                         uint32_t a2, uint32_t a3,
                                         uint32_t b0, uint32_t b1) {
    asm volatile(
        "mma.sync.aligned.m16n8k16.row.col.f32.f16.f16.f32 "
        "{%0,%1,%2,%3}, {%4,%5,%6,%7}, {%8,%9}, {%0,%1,%2,%3};"
        : "+f"(c[0]), "+f"(c[1]), "+f"(c[2]), "+f"(c[3])
        : "r"(a0), "r"(a1), "r"(a2), "r"(a3), "r"(b0), "r"(b1));
}
// pack two fp32 -> half2 reg {lo=a0, hi=a1}
__device__ __forceinline__ uint32_t packh2(float lo, float hi) {
    uint32_t d;
    asm("cvt.rn.f16x2.f32 %0, %1, %2;" : "=r"(d) : "f"(hi), "f"(lo));
    return d;
}
__device__ __forceinline__ unsigned short h_us(__half x) { return *(unsigned short*)&x; }

// ---------------------------------------------------------------- conversions
// in [M,1024] fp32 -> out [M,2048] fp16 as [hi | lo]
__global__ __launch_bounds__(256)
void split_rows_h(const float* __restrict__ in, __half* __restrict__ out)
{
    size_t e = ((size_t)blockIdx.x * 256 + threadIdx.x) * 4;
    int m = (int)(e >> 10);
    int k = (int)(e & 1023);
    float4 v = *(const float4*)(in + e);
    __half h[4], l[4];
#pragma unroll
    for (int i = 0; i < 4; i++) {
        float a = ((const float*)&v)[i];
        __half hb = __float2half_rn(a);
        h[i] = hb;
        l[i] = __float2half_rn(a - __half2float(hb));
    }
    size_t ob = (size_t)m * K2 + k;
    *(uint2*)(out + ob) = *(uint2*)h;
    *(uint2*)(out + ob + 1024) = *(uint2*)l;
}

// W [1024, Ncols] fp32 row-major -> out [Ncols, 2048] fp16 as [hi | hi]
__global__ __launch_bounds__(256)
void transpose_split_h(const float* __restrict__ in, __half* __restrict__ out, int Ncols)
{
    __shared__ float t[32][33];
    int k0 = blockIdx.y * 32;
    int n0 = blockIdx.x * 32;
    int tx = threadIdx.x & 31;
    int ty = threadIdx.x >> 5;
#pragma unroll
    for (int dy = 0; dy < 32; dy += 8)
        t[ty + dy][tx] = in[(size_t)(k0 + ty + dy) * Ncols + n0 + tx];
    __syncthreads();
#pragma unroll
    for (int dy = 0; dy < 32; dy += 8) {
        int n = n0 + ty + dy;
        __half hb = __float2half_rn(t[tx][ty + dy]);
        size_t ob = (size_t)n * K2 + k0 + tx;
        out[ob] = hb;
        out[ob + 1024] = hb;
    }
}

// ---------------------------------------------------------------- HMMA GEMM
// C[M,N] = A[M,K2] * B[N,K2]^T, fp16 in. HOUT: fp16 out (no bias); else fp32+bias.
#define BK 32
#define NKT (K2 / BK)            // 64
#define ROWB 80                  // padded row: 32 halfs + 8 pad = 80 bytes
#define ATILE (128 * ROWB)       // 10240 B
#define STAGEB (2 * ATILE)       // 20480 B
#define NSTAGE 4
#define GSMEM (NSTAGE * STAGEB)  // 81920 B

template <bool HOUT>
__global__ __launch_bounds__(256)
void gemm_hmma(const __half* __restrict__ A, const __half* __restrict__ B,
               void* __restrict__ Cv, const float* __restrict__ bias, int N)
{
    extern __shared__ char smem[];
    const uint32_t sbase = smem_u32(smem);

    const int tid = threadIdx.x;
    const int wid = tid >> 5;
    const int lane = tid & 31;
    const int wm = wid & 1;
    const int wn = wid >> 1;
    const int m0 = blockIdx.y * 128;
    const int n0 = blockIdx.x * 128;

    const __half* Ag = A + (size_t)m0 * K2;
    const __half* Bg = B + (size_t)n0 * K2;

    float acc[4][4][4];
#pragma unroll
    for (int i = 0; i < 4; i++)
#pragma unroll
        for (int j = 0; j < 4; j++)
#pragma unroll
            for (int r = 0; r < 4; r++) acc[i][j][r] = 0.f;

    auto load_stage = [&](int kt) {
        const uint32_t sa = sbase + (kt & (NSTAGE - 1)) * STAGEB;
        const uint32_t sb = sa + ATILE;
        const int koff = kt * BK;
#pragma unroll
        for (int i = 0; i < 2; i++) {
            int u = tid + i * 256;
            int row = u >> 2, seg = u & 3;
            cpa16(sa + row * ROWB + seg * 16,
                  Ag + (size_t)row * K2 + koff + seg * 8);
        }
#pragma unroll
        for (int i = 0; i < 2; i++) {
            int u = tid + i * 256;
            int row = u >> 2, seg = u & 3;
            cpa16(sb + row * ROWB + seg * 16,
                  Bg + (size_t)row * K2 + koff + seg * 8);
        }
        CP_COMMIT();
    };

    load_stage(0);
    load_stage(1);
    load_stage(2);

    const int a_row_off = ((lane >> 3) & 1) * 8 + (lane & 7);
    const int a_k_off   = ((lane >> 4) & 1) * 8;
    const int b_row_off = ((lane >> 4) & 1) * 8 + (lane & 7);
    const int b_k_off   = ((lane >> 3) & 1) * 8;

#pragma unroll 1
    for (int kt = 0; kt < NKT; kt++) {
        asm volatile("cp.async.wait_group 2;" ::: "memory");
        __syncthreads();
        const uint32_t sa = sbase + (kt & (NSTAGE - 1)) * STAGEB;
        const uint32_t sb = sa + ATILE;

#pragma unroll
        for (int ks = 0; ks < 2; ks++) {
            uint32_t af[4][4];
#pragma unroll
            for (int mi = 0; mi < 4; mi++) {
                uint32_t addr = sa + (wm * 64 + mi * 16 + a_row_off) * ROWB
                              + (ks * 16 + a_k_off) * 2;
                ldsm_x4(addr, af[mi][0], af[mi][1], af[mi][2], af[mi][3]);
            }
            uint32_t bf[4][2];
#pragma unroll
            for (int p = 0; p < 2; p++) {
                uint32_t addr = sb + (wn * 32 + p * 16 + b_row_off) * ROWB
                              + (ks * 16 + b_k_off) * 2;
                uint32_t r0, r1, r2, r3;
                ldsm_x4(addr, r0, r1, r2, r3);
                bf[p * 2 + 0][0] = r0; bf[p * 2 + 0][1] = r1;
                bf[p * 2 + 1][0] = r2; bf[p * 2 + 1][1] = r3;
            }
#pragma unroll
            for (int mi = 0; mi < 4; mi++)
#pragma unroll
                for (int ni = 0; ni < 4; ni++)
                    mma16816(acc[mi][ni], af[mi][0], af[mi][1], af[mi][2], af[mi][3],
                             bf[ni][0], bf[ni][1]);
        }

        if (kt + 3 < NKT) load_stage(kt + 3);
        else CP_COMMIT();
    }

    const int crow = lane >> 2;
    const int ccol = (lane & 3) * 2;
#pragma unroll
    for (int mi = 0; mi < 4; mi++) {
#pragma unroll
        for (int ni = 0; ni < 4; ni++) {
            int gm = m0 + wm * 64 + mi * 16 + crow;
            int gn = n0 + wn * 32 + ni * 8 + ccol;
            if (HOUT) {
                __half* C = (__half*)Cv;
                *(uint32_t*)&C[(size_t)gm * N + gn] = packh2(acc[mi][ni][0], acc[mi][ni][1]);
                *(uint32_t*)&C[(size_t)(gm + 8) * N + gn] = packh2(acc[mi][ni][2], acc[mi][ni][3]);
            } else {
                float* C = (float*)Cv;
                float b0 = bias ? bias[gn] : 0.f;
                float b1 = bias ? bias[gn + 1] : 0.f;
                float2 v0 = make_float2(acc[mi][ni][0] + b0, acc[mi][ni][1] + b1);
                float2 v1 = make_float2(acc[mi][ni][2] + b0, acc[mi][ni][3] + b1);
                *(float2*)&C[(size_t)gm * N + gn] = v0;
                *(float2*)&C[(size_t)(gm + 8) * N + gn] = v1;
            }
        }
    }
}

// ---------------------------------------------------------------- spatial attention (HMMA flash, async)
// Block: (nt, h, qhalf) -> 128 queries x 256 keys, Dh=64. 4 warps x 32 queries.
// Q fragments in registers; K/V double-buffered cp.async. Writes hi/lo fp16 to Ah.
#define AROW 72                       // 64 halfs + 8 pad (144 B rows)
__global__ __launch_bounds__(128)
void spatial_attn_h(const __half* __restrict__ qkvh, __half* __restrict__ Ah)
{
    const int b  = blockIdx.x;        // nt*16 + h*2 + qh
    const int qh = b & 1;
    const int h  = (b >> 1) & 7;
    const int nt = b >> 4;
    const size_t RS = QKV_COLS;
    const size_t rowbase = (size_t)nt * 256;
    const int q0 = qh * 128;

    __shared__ __half Kst[2][64 * AROW];
    __shared__ __half Vst[2][64 * AROW];

    const int tid  = threadIdx.x;
    const int warp = tid >> 5;
    const int lane = tid & 31;

    const uint32_t kb0 = smem_u32(Kst[0]);
    const uint32_t kb1 = smem_u32(Kst[1]);
    const uint32_t vb0 = smem_u32(Vst[0]);
    const uint32_t vb1 = smem_u32(Vst[1]);

    const int a_row_off = ((lane >> 3) & 1) * 8 + (lane & 7);
    const int a_k_off   = ((lane >> 4) & 1) * 8;
    const int b_row_off = ((lane >> 4) & 1) * 8 + (lane & 7);
    const int b_k_off   = ((lane >> 3) & 1) * 8;
    const int v_mat = lane >> 3;
    const int v_row_off = (v_mat & 1) * 8 + (lane & 7);
    const int v_col_off = (v_mat >> 1) * 8;

    // ---- stage Q (128 rows) through Kst[0..1], load fragments to regs
    for (int i = tid; i < 1024; i += 128) {
        int r = i >> 3, seg = i & 7;
        uint32_t dst = (r < 64 ? kb0 : kb1) + ((r & 63) * AROW + seg * 8) * 2;
        cpa16(dst, qkvh + (rowbase + q0 + r) * RS + h * 64 + seg * 8);
    }
    CP_COMMIT();
    asm volatile("cp.async.wait_group 0;" ::: "memory");
    __syncthreads();

    uint32_t qf[2][4][4];
    {
        const uint32_t qb = (warp < 2) ? kb0 : kb1;
        const int rbase = (warp & 1) * 32;
#pragma unroll
        for (int mi = 0; mi < 2; mi++)
#pragma unroll
            for (int kk = 0; kk < 4; kk++) {
                uint32_t addr = qb + (rbase + mi * 16 + a_row_off) * (AROW * 2)
                              + (kk * 16 + a_k_off) * 2;
                ldsm_x4(addr, qf[mi][kk][0], qf[mi][kk][1], qf[mi][kk][2], qf[mi][kk][3]);
            }
    }
    __syncthreads();   // all warps finished reading Q before KV overwrites

    auto load_kv = [&](int t, int s) {
        const uint32_t kb = s ? kb1 : kb0;
        const uint32_t vb = s ? vb1 : vb0;
        const size_t base = rowbase + t * 64;
        for (int i = tid; i < 512; i += 128) {
            int r = i >> 3, seg = i & 7;
            uint32_t off = (r * AROW + seg * 8) * 2;
            cpa16(kb + off, qkvh + (base + r) * RS + 1024 + h * 64 + seg * 8);
            cpa16(vb + off, qkvh + (base + r) * RS + 2048 + h * 64 + seg * 8);
        }
        CP_COMMIT();
    };
    load_kv(0, 0);

    float o[2][8][4];
#pragma unroll
    for (int mi = 0; mi < 2; mi++)
#pragma unroll
        for (int ni = 0; ni < 8; ni++)
#pragma unroll
            for (int r = 0; r < 4; r++) o[mi][ni][r] = 0.f;
    float mst[2][2] = {{-1e30f, -1e30f}, {-1e30f, -1e30f}};
    float lst[2][2] = {{0.f, 0.f}, {0.f, 0.f}};

#pragma unroll 1
    for (int t = 0; t < 4; t++) {
        __syncthreads();                       // all done with tile t-1 compute
        if (t + 1 < 4) {
            load_kv(t + 1, (t + 1) & 1);
            asm volatile("cp.async.wait_group 1;" ::: "memory");
        } else {
            asm volatile("cp.async.wait_group 0;" ::: "memory");
        }
        __syncthreads();                       // tile t visible to all

        const uint32_t kb = (t & 1) ? kb1 : kb0;
        const uint32_t vb = (t & 1) ? vb1 : vb0;

        // ---- S = Q K^T (32 x 64 per warp)
        float s[2][8][4];
#pragma unroll
        for (int mi = 0; mi < 2; mi++)
#pragma unroll
            for (int ni = 0; ni < 8; ni++)
#pragma unroll
                for (int r = 0; r < 4; r++) s[mi][ni][r] = 0.f;

#pragma unroll
        for (int kk = 0; kk < 4; kk++) {
            uint32_t bf[8][2];
#pragma unroll
            for (int kbk = 0; kbk < 4; kbk++) {
                uint32_t addr = kb + (kbk * 16 + b_row_off) * (AROW * 2)
                              + (kk * 16 + b_k_off) * 2;
                uint32_t r0, r1, r2, r3;
                ldsm_x4(addr, r0, r1, r2, r3);
                bf[kbk * 2 + 0][0] = r0; bf[kbk * 2 + 0][1] = r1;
                bf[kbk * 2 + 1][0] = r2; bf[kbk * 2 + 1][1] = r3;
            }
#pragma unroll
            for (int mi = 0; mi < 2; mi++)
#pragma unroll
                for (int ni = 0; ni < 8; ni++)
                    mma16816(s[mi][ni], qf[mi][kk][0], qf[mi][kk][1],
                             qf[mi][kk][2], qf[mi][kk][3], bf[ni][0], bf[ni][1]);
        }

        // scale logits
#pragma unroll
        for (int mi = 0; mi < 2; mi++)
#pragma unroll
            for (int ni = 0; ni < 8; ni++)
#pragma unroll
                for (int r = 0; r < 4; r++) s[mi][ni][r] *= 0.125f;

        // ---- online softmax
#pragma unroll
        for (int mi = 0; mi < 2; mi++) {
#pragma unroll
            for (int half = 0; half < 2; half++) {
                float mx = -1e30f;
#pragma unroll
                for (int ni = 0; ni < 8; ni++) {
                    mx = fmaxf(mx, s[mi][ni][half * 2 + 0]);
                    mx = fmaxf(mx, s[mi][ni][half * 2 + 1]);
                }
                mx = fmaxf(mx, __shfl_xor_sync(0xffffffffu, mx, 1));
                mx = fmaxf(mx, __shfl_xor_sync(0xffffffffu, mx, 2));
                float m_new = fmaxf(mst[mi][half], mx);
                float corr = __expf(mst[mi][half] - m_new);
                float sum = 0.f;
#pragma unroll
                for (int ni = 0; ni < 8; ni++) {
                    float p0 = __expf(s[mi][ni][half * 2 + 0] - m_new);
                    float p1 = __expf(s[mi][ni][half * 2 + 1] - m_new);
                    s[mi][ni][half * 2 + 0] = p0;
                    s[mi][ni][half * 2 + 1] = p1;
                    sum += p0 + p1;
                }
                sum += __shfl_xor_sync(0xffffffffu, sum, 1);
                sum += __shfl_xor_sync(0xffffffffu, sum, 2);
                lst[mi][half] = lst[mi][half] * corr + sum;
                mst[mi][half] = m_new;
#pragma unroll
                for (int ni = 0; ni < 8; ni++) {
                    o[mi][ni][half * 2 + 0] *= corr;
                    o[mi][ni][half * 2 + 1] *= corr;
                }
            }
        }

        // ---- O += P V
#pragma unroll
        for (int kk = 0; kk < 4; kk++) {
            uint32_t pa[2][4];
#pragma unroll
            for (int mi = 0; mi < 2; mi++) {
                pa[mi][0] = packh2(s[mi][kk * 2 + 0][0], s[mi][kk * 2 + 0][1]);
                pa[mi][1] = packh2(s[mi][kk * 2 + 0][2], s[mi][kk * 2 + 0][3]);
                pa[mi][2] = packh2(s[mi][kk * 2 + 1][0], s[mi][kk * 2 + 1][1]);
                pa[mi][3] = packh2(s[mi][kk * 2 + 1][2], s[mi][kk * 2 + 1][3]);
            }
#pragma unroll
            for (int nb = 0; nb < 4; nb++) {
                uint32_t addr = vb + (kk * 16 + v_row_off) * (AROW * 2)
                              + (nb * 16 + v_col_off) * 2;
                uint32_t b0, b1, b2, b3;
                ldsm_x4_t(addr, b0, b1, b2, b3);
#pragma unroll
                for (int mi = 0; mi < 2; mi++) {
                    mma16816(o[mi][nb * 2 + 0], pa[mi][0], pa[mi][1], pa[mi][2], pa[mi][3], b0, b1);
                    mma16816(o[mi][nb * 2 + 1], pa[mi][0], pa[mi][1], pa[mi][2], pa[mi][3], b2, b3);
                }
            }
        }
    }

    // ---- finalize: write hi/lo fp16 into Ah (attn cols 0..511 / +1024)
    const int crow = lane >> 2;
    const int ccol = (lane & 3) * 2;
#pragma unroll
    for (int mi = 0; mi < 2; mi++) {
        float inv0 = 1.f / lst[mi][0];
        float inv1 = 1.f / lst[mi][1];
        int row = q0 + warp * 32 + mi * 16 + crow;
#pragma unroll
        for (int ni = 0; ni < 8; ni++) {
            int col = h * 64 + ni * 8 + ccol;
            float f0 = o[mi][ni][0] * inv0, f1 = o[mi][ni][1] * inv0;
            float f2 = o[mi][ni][2] * inv1, f3 = o[mi][ni][3] * inv1;
            __half h0 = __float2half_rn(f0), h1 = __float2half_rn(f1);
            __half h2 = __float2half_rn(f2), h3 = __float2half_rn(f3);
            uint32_t hiA = (uint32_t)h_us(h0) | ((uint32_t)h_us(h1) << 16);
            uint32_t hiB = (uint32_t)h_us(h2) | ((uint32_t)h_us(h3) << 16);
            uint32_t loA = packh2(f0 - __half2float(h0), f1 - __half2float(h1));
            uint32_t loB = packh2(f2 - __half2float(h2), f3 - __half2float(h3));
            size_t mA = (rowbase + row) * K2;
            size_t mB = (rowbase + row + 8) * K2;
            *(uint32_t*)&Ah[mA + col] = hiA;
            *(uint32_t*)&Ah[mA + 1024 + col] = loA;
            *(uint32_t*)&Ah[mB + col] = hiB;
            *(uint32_t*)&Ah[mB + 1024 + col] = loB;
        }
    }
}

// ---------------------------------------------------------------- temporal attention (fp16 in, split fp16 out)
__global__ __launch_bounds__(128, 2)
void temporal_attn_h(const __half* __restrict__ qkvh, __half* __restrict__ Ah)
{
    const int b = blockIdx.x;
    const int n = b >> 8;
    const int s = b & 255;
    const int tid = threadIdx.x;
    const int h  = tid >> 4;
    const int qt = tid & 15;
    const size_t RS = QKV_COLS;

    __shared__ float Ks[16][512];
    __shared__ float Vs[16][512];

    for (int i = tid; i < 1024; i += 128) {
        int t = i >> 6;
        int c = (i & 63) * 8;
        size_t row = ((size_t)(n * 16 + t) * 256 + s);
        uint4 kr = *(const uint4*)&qkvh[row * RS + 1536 + c];
        uint4 vr = *(const uint4*)&qkvh[row * RS + 2560 + c];
        const __half2* kh = (const __half2*)&kr;
        const __half2* vh = (const __half2*)&vr;
#pragma unroll
        for (int j = 0; j < 4; j++) {
            float2 kf = __half22float2(kh[j]);
            float2 vf = __half22float2(vh[j]);
            Ks[t][c + 2 * j] = kf.x; Ks[t][c + 2 * j + 1] = kf.y;
            Vs[t][c + 2 * j] = vf.x; Vs[t][c + 2 * j + 1] = vf.y;
        }
    }
    __syncthreads();

    float q[64];
    const size_t qrow = ((size_t)(n * 16 + qt) * 256 + s);
#pragma unroll
    for (int d = 0; d < 64; d += 8) {
        uint4 qr = *(const uint4*)&qkvh[qrow * RS + 512 + h * 64 + d];
        const __half2* qp = (const __half2*)&qr;
#pragma unroll
        for (int j = 0; j < 4; j++) {
            float2 f = __half22float2(qp[j]);
            q[d + 2 * j] = f.x * 0.125f;
            q[d + 2 * j + 1] = f.y * 0.125f;
        }
    }

    float sc[16];
    float m = -1e30f;
#pragma unroll
    for (int t = 0; t < 16; t++) {
        float v = 0.f;
#pragma unroll
        for (int d = 0; d < 64; d++) v += q[d] * Ks[t][h * 64 + d];
        sc[t] = v;
        m = fmaxf(m, v);
    }
    float l = 0.f;
#pragma unroll
    for (int t = 0; t < 16; t++) { sc[t] = __expf(sc[t] - m); l += sc[t]; }
    float inv = 1.f / l;

    const size_t obase = qrow * K2 + 512 + (size_t)h * 64;   // hi at +0, lo at +1024
#pragma unroll
    for (int d = 0; d < 64; d += 4) {
        float f[4];
#pragma unroll
        for (int u = 0; u < 4; u++) {
            float acc = 0.f;
#pragma unroll
            for (int t = 0; t < 16; t++) acc += sc[t] * Vs[t][h * 64 + d + u];
            f[u] = acc * inv;
        }
        __half hh[4];
        unsigned short lo[4];
#pragma unroll
        for (int u = 0; u < 4; u++) {
            hh[u] = __float2half_rn(f[u]);
            __half lb = __float2half_rn(f[u] - __half2float(hh[u]));
            lo[u] = h_us(lb);
        }
        uint2 hw, lw;
        hw.x = (uint32_t)h_us(hh[0]) | ((uint32_t)h_us(hh[1]) << 16);
        hw.y = (uint32_t)h_us(hh[2]) | ((uint32_t)h_us(hh[3]) << 16);
        lw.x = (uint32_t)lo[0] | ((uint32_t)lo[1] << 16);
        lw.y = (uint32_t)lo[2] | ((uint32_t)lo[3] << 16);
        *(uint2*)&Ah[obase + d] = hw;
        *(uint2*)&Ah[obase + 1024 + d] = lw;
    }
}

// ---------------------------------------------------------------- launch
extern "C" void kernel_launch(void* const* d_in, const int* in_sizes, int n_in,
                              void* d_out, int out_size)
{
    const float* x     = (const float*)d_in[0];
    const float* Wqkv  = (const float*)d_in[1];
    const float* Wproj = (const float*)d_in[2];
    const float* bproj = (const float*)d_in[3];
    float*       out   = (float*)d_out;

    __half *qkvh = nullptr, *Ah = nullptr, *Bh = nullptr;
    cudaGetSymbolAddress((void**)&qkvh, g_qkvh);
    cudaGetSymbolAddress((void**)&Ah,   g_Ah);
    cudaGetSymbolAddress((void**)&Bh,   g_Bh);

    cudaFuncSetAttribute(gemm_hmma<true>,  cudaFuncAttributeMaxDynamicSharedMemorySize, GSMEM);
    cudaFuncSetAttribute(gemm_hmma<false>, cudaFuncAttributeMaxDynamicSharedMemorySize, GSMEM);

    // GEMM1: qkvh = fp16( x @ Wqkv )   (fp16 split over K2)
    split_rows_h<<<(M_ROWS * KK / 4) / 256, 256>>>(x, Ah);
    transpose_split_h<<<dim3(QKV_COLS / 32, KK / 32), 256>>>(Wqkv, Bh, QKV_COLS);
    gemm_hmma<true><<<dim3(QKV_COLS / 128, M_ROWS / 128), 256, GSMEM>>>(
        Ah, Bh, qkvh, nullptr, QKV_COLS);

    // attention: writes split-fp16 GEMM2 operand directly into Ah
    spatial_attn_h<<<512, 128>>>(qkvh, Ah);
    temporal_attn_h<<<512, 128>>>(qkvh, Ah);

    // GEMM2: out = attn @ Wproj + bproj
    transpose_split_h<<<dim3(D_MODEL / 32, KK / 32), 256>>>(Wproj, Bh, D_MODEL);
    gemm_hmma<false><<<dim3(D_MODEL / 128, M_ROWS / 128), 256, GSMEM>>>(
        Ah, Bh, out, bproj, D_MODEL);
}